// round 15
// baseline (speedup 1.0000x reference)
#include <cuda_runtime.h>
#include <cuda_bf16.h>
#include <cstdint>

// ---------------- problem sizes ----------------
#define NB   64
#define NS   2048
#define NDH  1024           // DEC_H (GEMM N total)
#define NEE  1024           // ENC2  (GEMM K)
#define MTOT (NB * NS)      // 131072 GEMM M

// GEMM tiling (R9 geometry: 256 thr, 8 warps 32x64, 2 CTAs/SM)
#define BM 128
#define BN 128
#define BK 64               // bf16 per chunk = 128 bytes/row (SW128 swizzle)
#define NKC (NEE / BK)      // 16 k-chunks
#define NTILES_N (NDH / BN) // 8
#define NSTAGE 3

#define SM_DP   0                    // 128 floats
#define SM_V    512
#define SM_SRED 1024                 // 2 * 128 floats
#define SM_ST   3072
#define STAGE_BYTES (BM * 128 + BN * 128)          // 32768 (A bf16 16K + B 16K)
#define SMEM_SZ (SM_ST + NSTAGE * STAGE_BYTES)     // 101376 -> 2 CTAs/SM

#define SWZ(o) ((o) ^ (((o) >> 3) & 0x70))

// context s-split
#define SSPLIT 8
#define SCHUNK (NS / SSPLIT)   // 256

// ---------------- device scratch ----------------
__device__ __nv_bfloat16 g_We[(size_t)NDH * NEE];     // 2 MB  bf16 We
__device__ float         g_dp[NB * NDH];              // dec_proj + W_b
__device__ float         g_part[(size_t)NTILES_N * MTOT]; // per-Ntile partials (4 MB)
__device__ float         g_att[MTOT];
__device__ float         g_ctxp[SSPLIT][NB * NEE];    // context partials (2 MB)

// ---------------- helpers ----------------
__device__ __forceinline__ uint32_t smem_u32(const void* p) {
    uint32_t a;
    asm("{ .reg .u64 t; cvta.to.shared.u64 t, %1; cvt.u32.u64 %0, t; }" : "=r"(a) : "l"(p));
    return a;
}
#define CP_ASYNC16(dst, src) \
    asm volatile("cp.async.cg.shared.global [%0], [%1], 16;" :: "r"(dst), "l"(src))
#define CP_COMMIT() asm volatile("cp.async.commit_group;" ::: "memory")
#define CP_WAIT1()  asm volatile("cp.async.wait_group 1;" ::: "memory")

#define LDM_X4(r0, r1, r2, r3, addr) \
    asm volatile("ldmatrix.sync.aligned.m8n8.x4.shared.b16 {%0,%1,%2,%3}, [%4];" \
                 : "=r"(r0), "=r"(r1), "=r"(r2), "=r"(r3) : "r"(addr))

#define STS128(addr, r0, r1, r2, r3) \
    asm volatile("st.shared.v4.b32 [%0], {%1,%2,%3,%4};" \
                 :: "r"(addr), "r"(r0), "r"(r1), "r"(r2), "r"(r3) : "memory")

__device__ __forceinline__ void mma_bf16(float* c, const uint32_t* a, const uint32_t* b) {
    asm volatile(
        "mma.sync.aligned.m16n8k16.row.col.f32.bf16.bf16.f32 "
        "{%0,%1,%2,%3}, {%4,%5,%6,%7}, {%8,%9}, {%0,%1,%2,%3};"
        : "+f"(c[0]), "+f"(c[1]), "+f"(c[2]), "+f"(c[3])
        : "r"(a[0]), "r"(a[1]), "r"(a[2]), "r"(a[3]), "r"(b[0]), "r"(b[1]));
}
__device__ __forceinline__ float fast_tanh(float x) {
    float e = __expf(2.0f * x);
    return 1.0f - 2.0f / (e + 1.0f);
}
__device__ __forceinline__ uint32_t pack_bf16(float a, float b) {
    __nv_bfloat162 t = __floats2bfloat162_rn(a, b);
    return *reinterpret_cast<uint32_t*>(&t);
}

// ====================== convert We ======================
__global__ void k_convert_we(const float* __restrict__ Ww) {
    int i = blockIdx.x * blockDim.x + threadIdx.x;   // quad id
    if (i >= NDH * NEE / 4) return;
    int d  = i >> 8;
    int e4 = (i & 255) * 4;
    float4 v = *reinterpret_cast<const float4*>(Ww + (size_t)d * 2048 + 1024 + e4);
    uint2 o;
    o.x = pack_bf16(v.x, v.y);
    o.y = pack_bf16(v.z, v.w);
    reinterpret_cast<uint2*>(g_We + (size_t)d * NEE + e4)[0] = o;
}

// ====================== dec_proj ======================
__global__ void k_decproj(const float* __restrict__ dh, const float* __restrict__ Ww,
                          const float* __restrict__ Wb) {
    int warp = (blockIdx.x * blockDim.x + threadIdx.x) >> 5;
    int lane = threadIdx.x & 31;
    #pragma unroll
    for (int i = 0; i < 4; i++) {
        int pair = warp * 4 + i;
        int b = pair & (NB - 1);
        int d = pair >> 6;
        const float4* wr = reinterpret_cast<const float4*>(Ww + (size_t)d * 2048);
        const float4* hr = reinterpret_cast<const float4*>(dh + (size_t)b * 1024);
        float acc = 0.f;
        #pragma unroll
        for (int k = lane; k < 256; k += 32) {
            float4 w = wr[k]; float4 h = hr[k];
            acc += w.x * h.x + w.y * h.y + w.z * h.z + w.w * h.w;
        }
        #pragma unroll
        for (int o = 16; o; o >>= 1) acc += __shfl_xor_sync(0xffffffffu, acc, o);
        if (lane == 0) g_dp[b * NDH + d] = acc + Wb[d];
    }
}

// ====================== scores GEMM: fused fp32->bf16 A load ======================
// Per-thread mapping (256 thr): r = tid>>1 (0..127), h = tid&1, chunks c = 4h+j.
// Swizzled chunk offset: r*128 + ((c ^ (r&7)) << 4).

__global__ void __launch_bounds__(256, 2) k_scores(const float* __restrict__ encf,
                                                   const float* __restrict__ vw) {
    extern __shared__ char smem[];
    uint32_t base = smem_u32(smem);
    float* sDP = (float*)(smem + SM_DP);
    float* sV  = (float*)(smem + SM_V);
    float* sR  = (float*)(smem + SM_SRED);   // [2][128]

    int tid = threadIdx.x;
    int wid = tid >> 5, lid = tid & 31;
    int g = lid >> 2, tig = lid & 3;
    int lr = lid & 15, lh = lid >> 4;        // ldmatrix lane row / 16B-half
    int warpM = wid & 3, warpN = wid >> 2;   // 4 x 2 warps -> 128 x 128, warp 32x64
    int ctaM = blockIdx.y * BM;
    int ctaN = blockIdx.x * BN;
    int b = ctaM >> 11;

    if (tid < BN) {
        sDP[tid] = g_dp[b * NDH + ctaN + tid];
        sV[tid]  = vw[ctaN + tid];
    }

    float acc[2][8][4];
    #pragma unroll
    for (int mt = 0; mt < 2; mt++)
        #pragma unroll
        for (int nt = 0; nt < 8; nt++)
            #pragma unroll
            for (int r = 0; r < 4; r++) acc[mt][nt][r] = 0.f;

    // per-thread load constants
    int r = tid >> 1, h = tid & 1;
    uint32_t soff[4];                        // swizzled 16B-chunk offsets (A and B share map)
    #pragma unroll
    for (int j = 0; j < 4; j++)
        soff[j] = (uint32_t)(r * 128 + (((4 * h + j) ^ (r & 7)) << 4));

    // A source: fp32 rows, 4096 B/row; per kc the 64-col window starts at kc*256 B
    const char* gaF = (const char*)encf + (size_t)(ctaM + r) * 4096 + h * 128;
    // B source: bf16 We rows, 2048 B/row; per kc window at kc*128 B
    const char* gbB = (const char*)g_We + (size_t)(ctaN + r) * 2048 + h * 64;

    uint4 areg[8];                           // one A stage in flight (fp32)

#define LD_A(kcv)                                                               \
    do {                                                                        \
        const char* p = gaF + (kcv) * 256;                                      \
        _Pragma("unroll")                                                       \
        for (int j = 0; j < 4; j++) {                                           \
            areg[2 * j]     = *reinterpret_cast<const uint4*>(p + j * 32);      \
            areg[2 * j + 1] = *reinterpret_cast<const uint4*>(p + j * 32 + 16); \
        }                                                                       \
    } while (0)

#define ST_A(stbase)                                                            \
    do {                                                                        \
        _Pragma("unroll")                                                       \
        for (int j = 0; j < 4; j++) {                                           \
            float4 lo = *reinterpret_cast<float4*>(&areg[2 * j]);               \
            float4 hi = *reinterpret_cast<float4*>(&areg[2 * j + 1]);           \
            uint32_t b0 = pack_bf16(lo.x, lo.y);                                \
            uint32_t b1 = pack_bf16(lo.z, lo.w);                                \
            uint32_t b2 = pack_bf16(hi.x, hi.y);                                \
            uint32_t b3 = pack_bf16(hi.z, hi.w);                                \
            STS128((stbase) + soff[j], b0, b1, b2, b3);                         \
        }                                                                       \
    } while (0)

#define LD_B(stbase, kcv)                                                       \
    do {                                                                        \
        const char* p = gbB + (kcv) * 128;                                      \
        _Pragma("unroll")                                                       \
        for (int j = 0; j < 4; j++)                                             \
            CP_ASYNC16((stbase) + BM * 128 + soff[j], p + j * 16);              \
    } while (0)

    // prologue: A stage0 -> smem, A stage1 -> regs, B stages 0,1 via cp.async
    LD_A(0);
    ST_A(base + SM_ST + 0 * STAGE_BYTES);
    LD_A(1);
    LD_B(base + SM_ST + 0 * STAGE_BYTES, 0);
    CP_COMMIT();
    LD_B(base + SM_ST + 1 * STAGE_BYTES, 1);
    CP_COMMIT();

    // pre-swizzled ldmatrix offsets
    uint32_t soff_a[2], soff_b[4];
    #pragma unroll
    for (int mt = 0; mt < 2; mt++)
        soff_a[mt] = SWZ((uint32_t)((warpM * 32 + mt * 16 + lr) * 128 + lh * 16));
    #pragma unroll
    for (int np = 0; np < 4; np++)
        soff_b[np] = (uint32_t)(BM * 128) +
                     SWZ((uint32_t)((warpN * 64 + np * 16 + lr) * 128 + lh * 16));

    for (int kc = 0; kc < NKC; kc++) {
        CP_WAIT1();                 // B stage kc resident (own groups)
        __syncthreads();            // all threads' B-kc + A-kc(STS) visible;
                                    // all warps done reading slot (kc-1)%3
        if (kc + 1 < NKC)
            ST_A(base + SM_ST + ((kc + 1) % NSTAGE) * STAGE_BYTES);  // from areg
        if (kc + 2 < NKC) {
            LD_A(kc + 2);                                            // refill areg
            LD_B(base + SM_ST + ((kc + 2) % NSTAGE) * STAGE_BYTES, kc + 2);
        }
        CP_COMMIT();

        uint32_t ab = base + SM_ST + (kc % NSTAGE) * STAGE_BYTES;
        #pragma unroll
        for (int s16 = 0; s16 < 4; s16++) {
            uint32_t af[2][4], bf[8][2];
            #pragma unroll
            for (int mt = 0; mt < 2; mt++)
                LDM_X4(af[mt][0], af[mt][1], af[mt][2], af[mt][3],
                       ab + (soff_a[mt] ^ (s16 * 32)));
            #pragma unroll
            for (int np = 0; np < 4; np++) {
                uint32_t r0, r1, r2, r3;
                LDM_X4(r0, r1, r2, r3, ab + (soff_b[np] ^ (s16 * 32)));
                bf[2 * np][0] = r0; bf[2 * np][1] = r2;
                bf[2 * np + 1][0] = r1; bf[2 * np + 1][1] = r3;
            }
            #pragma unroll
            for (int mt = 0; mt < 2; mt++)
                #pragma unroll
                for (int nt = 0; nt < 8; nt++)
                    mma_bf16(acc[mt][nt], af[mt], bf[nt]);
        }
    }
#undef LD_A
#undef ST_A
#undef LD_B

    // epilogue: partial score = sum_d v[d] * tanh(acc + dp[d])
    #pragma unroll
    for (int mt = 0; mt < 2; mt++) {
        float plo = 0.f, phi = 0.f;
        #pragma unroll
        for (int nt = 0; nt < 8; nt++) {
            int dl = warpN * 64 + nt * 8 + tig * 2;
            float d0 = sDP[dl], d1 = sDP[dl + 1];
            float v0 = sV[dl],  v1 = sV[dl + 1];
            plo += v0 * fast_tanh(acc[mt][nt][0] + d0) + v1 * fast_tanh(acc[mt][nt][1] + d1);
            phi += v0 * fast_tanh(acc[mt][nt][2] + d0) + v1 * fast_tanh(acc[mt][nt][3] + d1);
        }
        #pragma unroll
        for (int o = 1; o < 4; o <<= 1) {
            plo += __shfl_xor_sync(0xffffffffu, plo, o);
            phi += __shfl_xor_sync(0xffffffffu, phi, o);
        }
        if (tig == 0) {
            int rl = warpM * 32 + mt * 16 + g;
            sR[warpN * 128 + rl]     = plo;
            sR[warpN * 128 + rl + 8] = phi;
        }
    }
    __syncthreads();
    if (tid < 128)
        g_part[(size_t)blockIdx.x * MTOT + ctaM + tid] = sR[tid] + sR[128 + tid];
}

// ====================== softmax ======================
__global__ void k_softmax(const int* __restrict__ mask, float* __restrict__ out_w) {
    __shared__ float red[8];
    int bb = blockIdx.x, tid = threadIdx.x, lane = tid & 31, w = tid >> 5;
    float x[8];
    float mx = -3e38f;
    #pragma unroll
    for (int i = 0; i < 8; i++) {
        int s = tid + i * 256;
        float v = 0.f;
        #pragma unroll
        for (int nt = 0; nt < NTILES_N; nt++)
            v += g_part[(size_t)nt * MTOT + bb * NS + s];
        if (mask[bb * NS + s] == 0) v = -1e10f;
        x[i] = v;
        mx = fmaxf(mx, v);
    }
    #pragma unroll
    for (int o = 16; o; o >>= 1) mx = fmaxf(mx, __shfl_xor_sync(0xffffffffu, mx, o));
    if (lane == 0) red[w] = mx;
    __syncthreads();
    float bm = red[0];
    #pragma unroll
    for (int i = 1; i < 8; i++) bm = fmaxf(bm, red[i]);
    __syncthreads();
    float sum = 0.f;
    #pragma unroll
    for (int i = 0; i < 8; i++) { x[i] = expf(x[i] - bm); sum += x[i]; }
    #pragma unroll
    for (int o = 16; o; o >>= 1) sum += __shfl_xor_sync(0xffffffffu, sum, o);
    if (lane == 0) red[w] = sum;
    __syncthreads();
    float tot = 0.f;
    #pragma unroll
    for (int i = 0; i < 8; i++) tot += red[i];
    float inv = 1.0f / tot;
    #pragma unroll
    for (int i = 0; i < 8; i++) {
        int s = tid + i * 256;
        float ww = x[i] * inv;
        g_att[bb * NS + s] = ww;
        out_w[bb * NS + s] = ww;
    }
}

// ====================== context: s-split partials, MLP-16 ======================
__global__ void k_context_part(const float* __restrict__ enc) {
    int bb = blockIdx.y;
    int e = blockIdx.x * 256 + threadIdx.x;
    int s0 = blockIdx.z * SCHUNK;
    const float* ep = enc + (size_t)bb * NS * NEE + (size_t)s0 * NEE + e;
    const float* ap = g_att + bb * NS + s0;
    float a0 = 0.f, a1 = 0.f, a2 = 0.f, a3 = 0.f;
    for (int s = 0; s < SCHUNK; s += 16) {
        #pragma unroll
        for (int j = 0; j < 16; j += 4) {
            a0 += ap[s + j]     * ep[(size_t)(s + j)     * NEE];
            a1 += ap[s + j + 1] * ep[(size_t)(s + j + 1) * NEE];
            a2 += ap[s + j + 2] * ep[(size_t)(s + j + 2) * NEE];
            a3 += ap[s + j + 3] * ep[(size_t)(s + j + 3) * NEE];
        }
    }
    g_ctxp[blockIdx.z][bb * NEE + e] = (a0 + a1) + (a2 + a3);
}

__global__ void k_ctx_reduce(float* __restrict__ out_ctx) {
    int i = blockIdx.x * 256 + threadIdx.x;
    float acc = 0.f;
    #pragma unroll
    for (int z = 0; z < SSPLIT; z++) acc += g_ctxp[z][i];
    out_ctx[i] = acc;
}

// ====================== launch ======================
extern "C" void kernel_launch(void* const* d_in, const int* in_sizes, int n_in,
                              void* d_out, int out_size) {
    const float* dh   = (const float*)d_in[0];   // (1,64,1024)
    const float* enc  = (const float*)d_in[1];   // (64,2048,1024)
    const int*   mask = (const int*)  d_in[2];   // (64,1,2048)
    const float* Ww   = (const float*)d_in[3];   // (1024,2048)
    const float* Wb   = (const float*)d_in[4];   // (1024,)
    const float* vw   = (const float*)d_in[5];   // (1,1024)
    float* out = (float*)d_out;
    float* out_ctx = out;                        // (64,1,1024) first
    float* out_w   = out + NB * NEE;             // (64,2048) second

    cudaFuncSetAttribute(k_scores, cudaFuncAttributeMaxDynamicSharedMemorySize, SMEM_SZ);

    k_convert_we<<<NDH * NEE / 4 / 256, 256>>>(Ww);
    k_decproj<<<2048, 256>>>(dh, Ww, Wb);
    k_scores<<<dim3(NTILES_N, MTOT / BM), 256, SMEM_SZ>>>(enc, vw);
    k_softmax<<<NB, 256>>>(mask, out_w);
    k_context_part<<<dim3(NEE / 256, NB, SSPLIT), 256>>>(enc);
    k_ctx_reduce<<<NB * NEE / 256, 256>>>(out_ctx);
}

// round 16
// speedup vs baseline: 2.0389x; 2.0389x over previous
#include <cuda_runtime.h>
#include <cuda_bf16.h>
#include <cstdint>

// ---------------- problem sizes ----------------
#define NB   64
#define NS   2048
#define NDH  1024           // DEC_H (GEMM N total)
#define NEE  1024           // ENC2  (GEMM K)
#define MTOT (NB * NS)      // 131072 GEMM M

// GEMM tiling (R9 best: 256 thr, 8 warps 32x64, BN=128)
#define BM 128
#define BN 128
#define BK 64               // bf16 per chunk = 128 bytes/row (SW128 swizzle)
#define NKC (NEE / BK)      // 16 k-chunks
#define NTILES_N (NDH / BN) // 8
#define NSTAGE 3

#define SM_DP   0                    // 128 floats
#define SM_V    512
#define SM_SRED 1024                 // 2 * 128 floats
#define SM_ST   3072
#define STAGE_BYTES (BM * 128 + BN * 128)          // 32768
#define SMEM_SZ (SM_ST + NSTAGE * STAGE_BYTES)     // 101376

#define SWZ(o) ((o) ^ (((o) >> 3) & 0x70))

// context s-split
#define SSPLIT 8
#define SCHUNK (NS / SSPLIT)   // 256

// ---------------- device scratch ----------------
__device__ __nv_bfloat16 g_enc[(size_t)MTOT * NEE];   // 256 MB bf16 encoder
__device__ __nv_bfloat16 g_We[(size_t)NDH * NEE];     // 2 MB  bf16 We
__device__ float         g_dp[NB * NDH];              // dec_proj + W_b
__device__ float         g_part[(size_t)NTILES_N * MTOT]; // per-Ntile partials
__device__ float         g_att[MTOT];
__device__ float         g_ctxp[SSPLIT][NB * NEE];    // context partials (2 MB)

// ---------------- helpers ----------------
__device__ __forceinline__ uint32_t smem_u32(const void* p) {
    uint32_t a;
    asm("{ .reg .u64 t; cvta.to.shared.u64 t, %1; cvt.u32.u64 %0, t; }" : "=r"(a) : "l"(p));
    return a;
}
#define CP_ASYNC16(dst, src) \
    asm volatile("cp.async.cg.shared.global [%0], [%1], 16;" :: "r"(dst), "l"(src))
#define CP_COMMIT() asm volatile("cp.async.commit_group;" ::: "memory")
#define CP_WAIT1()  asm volatile("cp.async.wait_group 1;" ::: "memory")

#define LDM_X4(r0, r1, r2, r3, addr) \
    asm volatile("ldmatrix.sync.aligned.m8n8.x4.shared.b16 {%0,%1,%2,%3}, [%4];" \
                 : "=r"(r0), "=r"(r1), "=r"(r2), "=r"(r3) : "r"(addr))

__device__ __forceinline__ void mma_bf16(float* c, const uint32_t* a, const uint32_t* b) {
    asm volatile(
        "mma.sync.aligned.m16n8k16.row.col.f32.bf16.bf16.f32 "
        "{%0,%1,%2,%3}, {%4,%5,%6,%7}, {%8,%9}, {%0,%1,%2,%3};"
        : "+f"(c[0]), "+f"(c[1]), "+f"(c[2]), "+f"(c[3])
        : "r"(a[0]), "r"(a[1]), "r"(a[2]), "r"(a[3]), "r"(b[0]), "r"(b[1]));
}
__device__ __forceinline__ float fast_tanh(float x) {
    float e = __expf(2.0f * x);
    return 1.0f - 2.0f / (e + 1.0f);
}
__device__ __forceinline__ uint32_t pack_bf16(float a, float b) {
    __nv_bfloat162 t = __floats2bfloat162_rn(a, b);
    return *reinterpret_cast<uint32_t*>(&t);
}

// ====================== conversion: enc fp32 -> bf16 ======================
__global__ void k_convert_enc(const float* __restrict__ src) {
    const int n4 = MTOT * NEE / 4;
    const float4* s4 = (const float4*)src;
    uint2* d2 = reinterpret_cast<uint2*>(g_enc);
    for (int i = blockIdx.x * blockDim.x + threadIdx.x; i < n4;
         i += gridDim.x * blockDim.x) {
        float4 v = s4[i];
        uint2 o;
        o.x = pack_bf16(v.x, v.y);
        o.y = pack_bf16(v.z, v.w);
        d2[i] = o;
    }
}

// ====================== fused: convert We (blocks 0..1023) + dec_proj (1024..3071) ======================
__global__ void k_prep(const float* __restrict__ Ww, const float* __restrict__ dh,
                       const float* __restrict__ Wb) {
    if (blockIdx.x < 1024) {
        // We[d][e] = W_w[d][1024 + e], fp32 -> bf16
        int i = blockIdx.x * 256 + threadIdx.x;       // quad id, covers 1024*256*4 = NDH*NEE
        int d  = i >> 8;
        int e4 = (i & 255) * 4;
        float4 v = *reinterpret_cast<const float4*>(Ww + (size_t)d * 2048 + 1024 + e4);
        uint2 o;
        o.x = pack_bf16(v.x, v.y);
        o.y = pack_bf16(v.z, v.w);
        reinterpret_cast<uint2*>(g_We + (size_t)d * NEE + e4)[0] = o;
    } else {
        int warp = ((blockIdx.x - 1024) * 256 + threadIdx.x) >> 5;
        int lane = threadIdx.x & 31;
        #pragma unroll
        for (int i = 0; i < 4; i++) {
            int pair = warp * 4 + i;                  // 65536 pairs
            int b = pair & (NB - 1);
            int d = pair >> 6;
            const float4* wr = reinterpret_cast<const float4*>(Ww + (size_t)d * 2048);
            const float4* hr = reinterpret_cast<const float4*>(dh + (size_t)b * 1024);
            float acc = 0.f;
            #pragma unroll
            for (int k = lane; k < 256; k += 32) {
                float4 w = wr[k]; float4 h = hr[k];
                acc += w.x * h.x + w.y * h.y + w.z * h.z + w.w * h.w;
            }
            #pragma unroll
            for (int o = 16; o; o >>= 1) acc += __shfl_xor_sync(0xffffffffu, acc, o);
            if (lane == 0) g_dp[b * NDH + d] = acc + Wb[d];
        }
    }
}

// ====================== scores GEMM (R9 proven config) ======================
__device__ __forceinline__ void load_stage(uint32_t stbase, uint32_t sw0,
                                           const char* gaK, const char* gbK) {
    uint32_t bb = stbase + BM * 128;
    #pragma unroll
    for (int i = 0; i < 4; i++) {
        uint32_t sw = sw0 + i * 4096;
        CP_ASYNC16(stbase + sw, gaK + (size_t)i * 32 * (NEE * 2));
        CP_ASYNC16(bb + sw,     gbK + (size_t)i * 32 * (NEE * 2));
    }
}

__global__ void __launch_bounds__(256, 2) k_scores(const float* __restrict__ vw) {
    extern __shared__ char smem[];
    uint32_t base = smem_u32(smem);
    float* sDP = (float*)(smem + SM_DP);
    float* sV  = (float*)(smem + SM_V);
    float* sR  = (float*)(smem + SM_SRED);   // [2][128]

    int tid = threadIdx.x;
    int wid = tid >> 5, lid = tid & 31;
    int g = lid >> 2, tig = lid & 3;
    int lr = lid & 15, lh = lid >> 4;        // ldmatrix lane row / 16B-half
    int warpM = wid & 3, warpN = wid >> 2;   // 4 x 2 warps -> 128 x 128
    int ctaM = blockIdx.y * BM;
    int ctaN = blockIdx.x * BN;
    int b = ctaM >> 11;

    if (tid < 128) {
        sDP[tid] = g_dp[b * NDH + ctaN + tid];
        sV[tid]  = vw[ctaN + tid];
    }

    float acc[2][8][4];
    #pragma unroll
    for (int mt = 0; mt < 2; mt++)
        #pragma unroll
        for (int nt = 0; nt < 8; nt++)
            #pragma unroll
            for (int r = 0; r < 4; r++) acc[mt][nt][r] = 0.f;

    // cp.async per-thread constants; incremental gmem pointers
    int row0 = tid >> 3, q = tid & 7;
    uint32_t sw0 = SWZ((uint32_t)(row0 * 128 + q * 16));
    int grow0 = row0 * (NEE * 2) + q * 16;
    const char* gaK = (const char*)(g_enc + (size_t)ctaM * NEE) + grow0;
    const char* gbK = (const char*)(g_We + (size_t)ctaN * NEE) + grow0;

    // prologue: stages 0,1 (groups 0,1)
    load_stage(base + SM_ST + 0 * STAGE_BYTES, sw0, gaK, gbK);
    CP_COMMIT();
    load_stage(base + SM_ST + 1 * STAGE_BYTES, sw0, gaK + BK * 2, gbK + BK * 2);
    CP_COMMIT();
    gaK += 2 * BK * 2; gbK += 2 * BK * 2;

    // pre-swizzled ldmatrix offsets (bits 5-6 of raw offsets are zero)
    uint32_t soff_a[2], soff_b[4];
    #pragma unroll
    for (int mt = 0; mt < 2; mt++)
        soff_a[mt] = SWZ((uint32_t)((warpM * 32 + mt * 16 + lr) * 128 + lh * 16));
    #pragma unroll
    for (int np = 0; np < 4; np++)
        soff_b[np] = SWZ((uint32_t)((warpN * 64 + np * 16 + lr) * 128 + lh * 16));

    for (int kc = 0; kc < NKC; kc++) {
        CP_WAIT1();                 // own groups drained through stage kc
        __syncthreads();            // stage-kc writes visible; slot (kc-1)%3 free
        if (kc + 2 < NKC) {
            load_stage(base + SM_ST + ((kc + 2) % NSTAGE) * STAGE_BYTES, sw0,
                       gaK, gbK);
            gaK += BK * 2; gbK += BK * 2;
        }
        CP_COMMIT();

        uint32_t ab = base + SM_ST + (kc % NSTAGE) * STAGE_BYTES;
        uint32_t bb = ab + BM * 128;
        #pragma unroll
        for (int s16 = 0; s16 < 4; s16++) {
            uint32_t af[2][4], bf[8][2];
            #pragma unroll
            for (int mt = 0; mt < 2; mt++)
                LDM_X4(af[mt][0], af[mt][1], af[mt][2], af[mt][3],
                       ab + (soff_a[mt] ^ (s16 * 32)));
            #pragma unroll
            for (int np = 0; np < 4; np++) {
                uint32_t r0, r1, r2, r3;
                LDM_X4(r0, r1, r2, r3, bb + (soff_b[np] ^ (s16 * 32)));
                bf[2 * np][0] = r0; bf[2 * np][1] = r2;
                bf[2 * np + 1][0] = r1; bf[2 * np + 1][1] = r3;
            }
            #pragma unroll
            for (int mt = 0; mt < 2; mt++)
                #pragma unroll
                for (int nt = 0; nt < 8; nt++)
                    mma_bf16(acc[mt][nt], af[mt], bf[nt]);
        }
    }

    // epilogue: partial score = sum_d v[d] * tanh(acc + dp[d])
    #pragma unroll
    for (int mt = 0; mt < 2; mt++) {
        float plo = 0.f, phi = 0.f;
        #pragma unroll
        for (int nt = 0; nt < 8; nt++) {
            int dl = warpN * 64 + nt * 8 + tig * 2;
            float d0 = sDP[dl], d1 = sDP[dl + 1];
            float v0 = sV[dl],  v1 = sV[dl + 1];
            plo += v0 * fast_tanh(acc[mt][nt][0] + d0) + v1 * fast_tanh(acc[mt][nt][1] + d1);
            phi += v0 * fast_tanh(acc[mt][nt][2] + d0) + v1 * fast_tanh(acc[mt][nt][3] + d1);
        }
        #pragma unroll
        for (int o = 1; o < 4; o <<= 1) {
            plo += __shfl_xor_sync(0xffffffffu, plo, o);
            phi += __shfl_xor_sync(0xffffffffu, phi, o);
        }
        if (tig == 0) {
            int rl = warpM * 32 + mt * 16 + g;
            sR[warpN * 128 + rl]     = plo;
            sR[warpN * 128 + rl + 8] = phi;
        }
    }
    __syncthreads();
    if (tid < 128)
        g_part[(size_t)blockIdx.x * MTOT + ctaM + tid] = sR[tid] + sR[128 + tid];
}

// ====================== softmax ======================
__global__ void k_softmax(const int* __restrict__ mask, float* __restrict__ out_w) {
    __shared__ float red[8];
    int bb = blockIdx.x, tid = threadIdx.x, lane = tid & 31, w = tid >> 5;
    float x[8];
    float mx = -3e38f;
    #pragma unroll
    for (int i = 0; i < 8; i++) {
        int s = tid + i * 256;
        float v = 0.f;
        #pragma unroll
        for (int nt = 0; nt < NTILES_N; nt++)
            v += g_part[(size_t)nt * MTOT + bb * NS + s];
        if (mask[bb * NS + s] == 0) v = -1e10f;
        x[i] = v;
        mx = fmaxf(mx, v);
    }
    #pragma unroll
    for (int o = 16; o; o >>= 1) mx = fmaxf(mx, __shfl_xor_sync(0xffffffffu, mx, o));
    if (lane == 0) red[w] = mx;
    __syncthreads();
    float bm = red[0];
    #pragma unroll
    for (int i = 1; i < 8; i++) bm = fmaxf(bm, red[i]);
    __syncthreads();
    float sum = 0.f;
    #pragma unroll
    for (int i = 0; i < 8; i++) { x[i] = __expf(x[i] - bm); sum += x[i]; }
    #pragma unroll
    for (int o = 16; o; o >>= 1) sum += __shfl_xor_sync(0xffffffffu, sum, o);
    if (lane == 0) red[w] = sum;
    __syncthreads();
    float tot = 0.f;
    #pragma unroll
    for (int i = 0; i < 8; i++) tot += red[i];
    float inv = 1.0f / tot;
    #pragma unroll
    for (int i = 0; i < 8; i++) {
        int s = tid + i * 256;
        float ww = x[i] * inv;
        g_att[bb * NS + s] = ww;
        out_w[bb * NS + s] = ww;
    }
}

// ====================== context: s-split partials, MLP-16 ======================
__global__ void k_context_part(const float* __restrict__ enc) {
    int bb = blockIdx.y;
    int e = blockIdx.x * 256 + threadIdx.x;
    int s0 = blockIdx.z * SCHUNK;
    const float* ep = enc + (size_t)bb * NS * NEE + (size_t)s0 * NEE + e;
    const float* ap = g_att + bb * NS + s0;
    float a0 = 0.f, a1 = 0.f, a2 = 0.f, a3 = 0.f;
    for (int s = 0; s < SCHUNK; s += 16) {
        #pragma unroll
        for (int j = 0; j < 16; j += 4) {
            a0 += ap[s + j]     * ep[(size_t)(s + j)     * NEE];
            a1 += ap[s + j + 1] * ep[(size_t)(s + j + 1) * NEE];
            a2 += ap[s + j + 2] * ep[(size_t)(s + j + 2) * NEE];
            a3 += ap[s + j + 3] * ep[(size_t)(s + j + 3) * NEE];
        }
    }
    g_ctxp[blockIdx.z][bb * NEE + e] = (a0 + a1) + (a2 + a3);
}

__global__ void k_ctx_reduce(float* __restrict__ out_ctx) {
    int i = blockIdx.x * 256 + threadIdx.x;
    float acc = 0.f;
    #pragma unroll
    for (int z = 0; z < SSPLIT; z++) acc += g_ctxp[z][i];
    out_ctx[i] = acc;
}

// ====================== launch ======================
extern "C" void kernel_launch(void* const* d_in, const int* in_sizes, int n_in,
                              void* d_out, int out_size) {
    const float* dh   = (const float*)d_in[0];   // (1,64,1024)
    const float* enc  = (const float*)d_in[1];   // (64,2048,1024)
    const int*   mask = (const int*)  d_in[2];   // (64,1,2048)
    const float* Ww   = (const float*)d_in[3];   // (1024,2048)
    const float* Wb   = (const float*)d_in[4];   // (1024,)
    const float* vw   = (const float*)d_in[5];   // (1,1024)
    float* out = (float*)d_out;
    float* out_ctx = out;                        // (64,1,1024) first
    float* out_w   = out + NB * NEE;             // (64,2048) second

    cudaFuncSetAttribute(k_scores, cudaFuncAttributeMaxDynamicSharedMemorySize, SMEM_SZ);

    k_convert_enc<<<2048, 256>>>(enc);
    k_prep<<<3072, 256>>>(Ww, dh, Wb);
    k_scores<<<dim3(NTILES_N, MTOT / BM), 256, SMEM_SZ>>>(vw);
    k_softmax<<<NB, 256>>>(mask, out_w);
    k_context_part<<<dim3(NEE / 256, NB, SSPLIT), 256>>>(enc);
    k_ctx_reduce<<<NB * NEE / 256, 256>>>(out_ctx);
}